// round 15
// baseline (speedup 1.0000x reference)
#include <cuda_runtime.h>
#include <cuda_bf16.h>
#include <cstdint>

#define BATCH 4
#define CDIM 128
#define IDIM 64
#define NPIX 4096
#define LOG2E 1.4426950408889634f
#define SKV 72

// ---------------- device scratch ----------------
__device__ __align__(128) __nv_bfloat16 g_Wb[6 * CDIM * IDIM];                   // [p][c][i] bf16
__device__ __align__(128) __nv_bfloat16 g_WlB[IDIM * IDIM];                      // wWl bf16
__device__ __align__(128) __nv_bfloat16 g_WB[CDIM * IDIM];                       // wW  bf16
__device__ __align__(128) __nv_bfloat16 g_proj[(size_t)6 * BATCH * NPIX * IDIM]; // [p][b][n][i]
__device__ __align__(128) __nv_bfloat16 g_yb[(size_t)2 * BATCH * NPIX * IDIM];   // [br][b][n][i] bf16

// ---------------- generic helpers ----------------
__device__ __forceinline__ uint32_t smaddr(const void* p) {
    return (uint32_t)__cvta_generic_to_shared(p);
}
__device__ __forceinline__ uint32_t packbf(float lo, float hi) {
    uint32_t r;
    asm("cvt.rn.bf16x2.f32 %0, %1, %2;" : "=r"(r) : "f"(hi), "f"(lo));
    return r;
}
__device__ __forceinline__ float2 unpackbf(uint32_t u) {
    __nv_bfloat162 h = *(__nv_bfloat162*)&u;
    return make_float2(__bfloat162float(h.x), __bfloat162float(h.y));
}
__device__ __forceinline__ uint32_t ex2b(uint32_t x) {   // 2^x on packed bf16x2
    uint32_t y;
    asm("ex2.approx.ftz.bf16x2 %0, %1;" : "=r"(y) : "r"(x));
    return y;
}
__device__ __forceinline__ void cpa16(uint32_t dst, const void* src) {
    asm volatile("cp.async.cg.shared.global [%0], [%1], 16;" :: "r"(dst), "l"(src));
}
#define CP_COMMIT asm volatile("cp.async.commit_group;")
#define CP_WAIT(n) asm volatile("cp.async.wait_group %0;" :: "n"(n))

// ---------------- mma helpers ----------------
__device__ __forceinline__ void ldmx4(uint32_t r[4], const void* p) {
    asm volatile("ldmatrix.sync.aligned.m8n8.x4.shared.b16 {%0,%1,%2,%3}, [%4];"
                 : "=r"(r[0]), "=r"(r[1]), "=r"(r[2]), "=r"(r[3]) : "r"(smaddr(p)));
}
__device__ __forceinline__ void ldmx4t(uint32_t r[4], const void* p) {
    asm volatile("ldmatrix.sync.aligned.m8n8.x4.trans.shared.b16 {%0,%1,%2,%3}, [%4];"
                 : "=r"(r[0]), "=r"(r[1]), "=r"(r[2]), "=r"(r[3]) : "r"(smaddr(p)));
}
__device__ __forceinline__ void ldmx2(uint32_t r[2], const void* p) {
    asm volatile("ldmatrix.sync.aligned.m8n8.x2.shared.b16 {%0,%1}, [%2];"
                 : "=r"(r[0]), "=r"(r[1]) : "r"(smaddr(p)));
}
__device__ __forceinline__ void ldmx2t(uint32_t r[2], const void* p) {
    asm volatile("ldmatrix.sync.aligned.m8n8.x2.trans.shared.b16 {%0,%1}, [%2];"
                 : "=r"(r[0]), "=r"(r[1]) : "r"(smaddr(p)));
}
__device__ __forceinline__ void mma16816(float d[4], const uint32_t a[4], const uint32_t b[2]) {
    asm volatile("mma.sync.aligned.m16n8k16.row.col.f32.bf16.bf16.f32 "
                 "{%0,%1,%2,%3}, {%4,%5,%6,%7}, {%8,%9}, {%0,%1,%2,%3};"
                 : "+f"(d[0]), "+f"(d[1]), "+f"(d[2]), "+f"(d[3])
                 : "r"(a[0]), "r"(a[1]), "r"(a[2]), "r"(a[3]), "r"(b[0]), "r"(b[1]));
}

// ---------------- kernel 0: weight prep ----------------
__global__ void prep_wt_kernel(const float* __restrict__ w0, const float* __restrict__ w1,
                               const float* __restrict__ w2, const float* __restrict__ w3,
                               const float* __restrict__ w4, const float* __restrict__ w5,
                               const float* __restrict__ wWl, const float* __restrict__ wW) {
    int idx = blockIdx.x * blockDim.x + threadIdx.x;
    if (idx < 6 * CDIM * IDIM) {
        int p = idx / (CDIM * IDIM);
        int r = idx % (CDIM * IDIM);
        int c = r / IDIM, i = r % IDIM;
        const float* w = (p == 0) ? w0 : (p == 1) ? w1 : (p == 2) ? w2 : (p == 3) ? w3 : (p == 4) ? w4 : w5;
        float s = (p == 0 || p == 2) ? LOG2E : 1.0f;
        g_Wb[idx] = __float2bfloat16(w[i * CDIM + c] * s);
    } else if (idx < 6 * CDIM * IDIM + IDIM * IDIM) {
        int k = idx - 6 * CDIM * IDIM;
        g_WlB[k] = __float2bfloat16(wWl[k]);
    } else if (idx < 6 * CDIM * IDIM + IDIM * IDIM + CDIM * IDIM) {
        int k = idx - 6 * CDIM * IDIM - IDIM * IDIM;
        g_WB[k] = __float2bfloat16(wW[k]);
    }
}

// ---------------- kernel 1: fused projections (tensor core, proven) ----------------
#define APAD 72
__global__ __launch_bounds__(128) void proj_kernel(
    const float* __restrict__ x, const float* __restrict__ mask,
    const float* __restrict__ b0, const float* __restrict__ b1,
    const float* __restrict__ b2, const float* __restrict__ b3,
    const float* __restrict__ b4, const float* __restrict__ b5)
{
    __shared__ __align__(16) __nv_bfloat16 As[CDIM * APAD];   // [c][px]
    __shared__ __align__(16) __nv_bfloat16 Bs[CDIM * APAD];   // [c][i]
    __shared__ float maskS[64];

    int n0 = blockIdx.x * 64;
    int b  = blockIdx.y;
    int t  = threadIdx.x;
    int lane = t & 31, w = t >> 5;
    int gID = lane >> 2, tig = lane & 3;

    for (int idx = t; idx < 1024; idx += 128) {
        int c = idx >> 3, px0 = (idx & 7) * 8;
        const float* xr = x + ((size_t)b * CDIM + c) * NPIX + n0 + px0;
        float4 v0 = *(const float4*)xr;
        float4 v1 = *(const float4*)(xr + 4);
        uint4 pk;
        pk.x = packbf(v0.x, v0.y); pk.y = packbf(v0.z, v0.w);
        pk.z = packbf(v1.x, v1.y); pk.w = packbf(v1.z, v1.w);
        *(uint4*)&As[c * APAD + px0] = pk;
    }
    if (t < 64) maskS[t] = mask[(size_t)b * NPIX + n0 + t];
    __syncthreads();

    uint32_t af[8][4];
#pragma unroll
    for (int kt = 0; kt < 8; kt++) {
        const __nv_bfloat16* ap =
            &As[(kt * 16 + (lane & 7) + ((lane >> 4) << 3)) * APAD + w * 16 + (((lane >> 3) & 1) << 3)];
        ldmx4t(af[kt], ap);
    }

    const float* biases[6] = {b0, b1, b2, b3, b4, b5};
    int px0 = w * 16 + gID;

#pragma unroll
    for (int p = 0; p < 6; p++) {
        __syncthreads();
        const __nv_bfloat16* wsrc = g_Wb + p * (CDIM * IDIM);
        for (int idx = t; idx < 512; idx += 128) {
            int c = idx >> 2, c8 = (idx & 3) * 16;
            *(uint4*)&Bs[c * APAD + c8]     = *(const uint4*)&wsrc[c * IDIM + c8];
            *(uint4*)&Bs[c * APAD + c8 + 8] = *(const uint4*)&wsrc[c * IDIM + c8 + 8];
        }
        __syncthreads();

        float C[8][4];
#pragma unroll
        for (int nt = 0; nt < 8; nt++) C[nt][0] = C[nt][1] = C[nt][2] = C[nt][3] = 0.f;
#pragma unroll
        for (int kt = 0; kt < 8; kt++) {
#pragma unroll
            for (int nt = 0; nt < 8; nt++) {
                uint32_t bf[2];
                ldmx2t(bf, &Bs[(kt * 16 + (lane & 15)) * APAD + nt * 8]);
                mma16816(C[nt], af[kt], bf);
            }
        }

        bool um = (p == 2 || p == 3);
        float bscale = (p == 0 || p == 2) ? LOG2E : 1.0f;
        float mv0 = um ? maskS[px0] : 1.f;
        float mv1 = um ? maskS[px0 + 8] : 1.f;
        const float* biasp = biases[p];

        __nv_bfloat16* outp = g_proj + ((size_t)(p * BATCH + b) * NPIX + n0) * IDIM;
#pragma unroll
        for (int nt = 0; nt < 8; nt++) {
            int i2 = nt * 8 + tig * 2;
            float bb0 = biasp[i2] * bscale, bb1 = biasp[i2 + 1] * bscale;
            *(uint32_t*)&outp[(size_t)px0 * IDIM + i2] =
                packbf((C[nt][0] + bb0) * mv0, (C[nt][1] + bb1) * mv0);
            *(uint32_t*)&outp[(size_t)(px0 + 8) * IDIM + i2] =
                packbf((C[nt][2] + bb0) * mv1, (C[nt][3] + bb1) * mv1);
        }
    }
}

// ---------------- kernel 2: flash attention (3-stage ring, single sync per tile) ----------------
#define STAGE_BYTES (128 * SKV * 2)           // K(64 rows)+V(64 rows), 18432 B
#define ATTN_DSMEM (3 * STAGE_BYTES)

__device__ __forceinline__ void prefKV(__nv_bfloat16* dst, const __nv_bfloat16* Kt,
                                       const __nv_bfloat16* Vt, int t) {
    for (int idx = t; idx < 512; idx += 256) {
        int r = idx >> 3, c8 = (idx & 7) * 8;
        cpa16(smaddr(&dst[r * SKV + c8]), &Kt[(size_t)r * IDIM + c8]);
        cpa16(smaddr(&dst[64 * SKV + r * SKV + c8]), &Vt[(size_t)r * IDIM + c8]);
    }
}

__global__ __launch_bounds__(256, 2) void attn_kernel() {
    extern __shared__ __align__(16) uint8_t dynsm[];
    int qt = blockIdx.x, b = blockIdx.y, br = blockIdx.z;
    int t = threadIdx.x, lane = t & 31, w = t >> 5;
    int gID = lane >> 2, tig = lane & 3;

    __nv_bfloat16* stg[3] = {(__nv_bfloat16*)dynsm,
                             (__nv_bfloat16*)(dynsm + STAGE_BYTES),
                             (__nv_bfloat16*)(dynsm + 2 * STAGE_BYTES)};

    const __nv_bfloat16* Qg = g_proj + ((size_t)(br * 2 + 0) * BATCH + b) * NPIX * IDIM
                                     + (size_t)qt * 128 * IDIM;
    const __nv_bfloat16* Kg = g_proj + ((size_t)(br * 2 + 1) * BATCH + b) * NPIX * IDIM;
    const __nv_bfloat16* Vg = g_proj + ((size_t)(4 + br) * BATCH + b) * NPIX * IDIM;

    // stage 128 Q rows in stage0, pull A fragments
    for (int idx = t; idx < 1024; idx += 256) {
        int r = idx >> 3, c8 = (idx & 7) * 8;
        *(uint4*)&stg[0][r * SKV + c8] = *(const uint4*)&Qg[(size_t)r * IDIM + c8];
    }
    __syncthreads();
    uint32_t qa[4][4];
    {
        const __nv_bfloat16* qbase = &stg[0][(w * 16 + (lane & 15)) * SKV + (lane >> 4) * 8];
#pragma unroll
        for (int kk = 0; kk < 4; kk++) ldmx4(qa[kk], qbase + kk * 16);
    }
    __syncthreads();

    prefKV(stg[0], Kg, Vg, t);                         CP_COMMIT;   // tile 0
    prefKV(stg[1], Kg + 64 * IDIM, Vg + 64 * IDIM, t); CP_COMMIT;   // tile 1

    const uint32_t ones2[2] = {0x3F803F80u, 0x3F803F80u};
    float Lacc[4] = {0.f, 0.f, 0.f, 0.f};
    float O[8][4];
#pragma unroll
    for (int d = 0; d < 8; d++) O[d][0] = O[d][1] = O[d][2] = O[d][3] = 0.f;

    for (int kt = 0; kt < 64; kt++) {
        CP_WAIT(1);          // own share of tile kt done
        __syncthreads();     // all shares visible; all warps past tile kt-1 (reuse guard)
        if (kt + 2 < 64)
            prefKV(stg[(kt + 2) % 3],
                   Kg + (size_t)(kt + 2) * 64 * IDIM,
                   Vg + (size_t)(kt + 2) * 64 * IDIM, t);
        CP_COMMIT;           // unconditional: keeps group counting uniform

        const __nv_bfloat16* Ks = stg[kt % 3];
        const __nv_bfloat16* Vs = Ks + 64 * SKV;

        float S[8][4];
#pragma unroll
        for (int nt = 0; nt < 8; nt++) {
            S[nt][0] = S[nt][1] = S[nt][2] = S[nt][3] = 0.f;
#pragma unroll
            for (int ks = 0; ks < 4; ks++) {
                uint32_t kb[2];
                ldmx2(kb, &Ks[(nt * 8 + (lane & 7)) * SKV + ks * 16 + ((lane >> 3) & 1) * 8]);
                mma16816(S[nt], qa[ks], kb);
            }
        }

        uint32_t pa[4][4];
#pragma unroll
        for (int nt = 0; nt < 8; nt++) {
            pa[nt >> 1][(nt & 1) * 2 + 0] = ex2b(packbf(S[nt][0], S[nt][1]));
            pa[nt >> 1][(nt & 1) * 2 + 1] = ex2b(packbf(S[nt][2], S[nt][3]));
        }

#pragma unroll
        for (int ks = 0; ks < 4; ks++) mma16816(Lacc, pa[ks], ones2);

#pragma unroll
        for (int d = 0; d < 8; d++) {
#pragma unroll
            for (int ks = 0; ks < 4; ks++) {
                uint32_t vb[2];
                ldmx2t(vb, &Vs[(ks * 16 + (lane & 15)) * SKV + d * 8]);
                mma16816(O[d], pa[ks], vb);
            }
        }
    }

    float inv0 = 1.f / Lacc[0], inv1 = 1.f / Lacc[2];

    int r0 = qt * 128 + w * 16 + gID;
    __nv_bfloat16* yb = g_yb + ((size_t)br * BATCH + b) * NPIX * IDIM;
#pragma unroll
    for (int d = 0; d < 8; d++) {
        int col = d * 8 + tig * 2;
        *(uint32_t*)&yb[(size_t)r0 * IDIM + col] =
            packbf(O[d][0] * inv0, O[d][1] * inv0);
        *(uint32_t*)&yb[(size_t)(r0 + 8) * IDIM + col] =
            packbf(O[d][2] * inv1, O[d][3] * inv1);
    }
}

// ---------------- kernel 3: tensor-core fused epilogue, 32-px tiles, grid 512 ----------------
// layout: yls 0 | ynlS 4608 | ycs 9216 | wWls 13824 | wWs 23040..41472
// outS (18432 B) aliases [0, 18432) after ycs consumed into af2 (wWls dead after stage A).
#define EPI_DSMEM 41472
__global__ __launch_bounds__(256) void epi_kernel(
    const float* __restrict__ x,
    const float* __restrict__ gWl, const float* __restrict__ betaWl,
    const float* __restrict__ bW,  const float* __restrict__ gW,
    const float* __restrict__ betaW,
    float* __restrict__ out)
{
    extern __shared__ __align__(16) uint8_t esm[];
    __nv_bfloat16* yls  = (__nv_bfloat16*)(esm);
    __nv_bfloat16* ynlS = (__nv_bfloat16*)(esm + 4608);
    __nv_bfloat16* ycs  = (__nv_bfloat16*)(esm + 9216);
    __nv_bfloat16* wWls = (__nv_bfloat16*)(esm + 13824);
    __nv_bfloat16* wWs  = (__nv_bfloat16*)(esm + 23040);
    float*         outS = (float*)(esm);          // aliases yls/ynlS/ycs/part of wWls

    int b = blockIdx.y, n0 = blockIdx.x * 32;
    int t = threadIdx.x, lane = t & 31, w = t >> 5;
    int gID = lane >> 2, tig = lane & 3;
    int wr = w & 1;          // row group (16 px)
    int wc = w >> 1;         // column quarter (0..3)

    const __nv_bfloat16* ylg  = g_yb + ((size_t)(BATCH + b) * NPIX + n0) * IDIM;
    const __nv_bfloat16* ynlg = g_yb + ((size_t)b * NPIX + n0) * IDIM;

    {
        int r = t >> 3, c8 = (t & 7) * 8;          // 256 threads = 256 chunks (32 rows x 8)
        *(uint4*)&yls[r * APAD + c8]  = *(const uint4*)&ylg[(size_t)r * IDIM + c8];
        *(uint4*)&ynlS[r * APAD + c8] = *(const uint4*)&ynlg[(size_t)r * IDIM + c8];
    }
    for (int idx = t; idx < 512; idx += 256) {
        int r = idx >> 3, c8 = (idx & 7) * 8;
        *(uint4*)&wWls[r * APAD + c8] = *(const uint4*)&g_WlB[r * IDIM + c8];
    }
    for (int idx = t; idx < 1024; idx += 256) {
        int r = idx >> 3, c8 = (idx & 7) * 8;
        *(uint4*)&wWs[r * APAD + c8] = *(const uint4*)&g_WB[r * IDIM + c8];
    }
    __syncthreads();

    float rs = rsqrtf(1.0f + 1e-5f);
    int px0 = wr * 16 + gID;

    // stage A GEMM: C[px][i] = y_l @ wWl^T — each warp: 2 of 8 nt
    uint32_t af[4][4];
    {
        const __nv_bfloat16* ab = &yls[(wr * 16 + (lane & 15)) * APAD + (lane >> 4) * 8];
#pragma unroll
        for (int ks = 0; ks < 4; ks++) ldmx4(af[ks], ab + ks * 16);
    }
    float C[2][4];
#pragma unroll
    for (int nn = 0; nn < 2; nn++) C[nn][0] = C[nn][1] = C[nn][2] = C[nn][3] = 0.f;
#pragma unroll
    for (int nn = 0; nn < 2; nn++) {
        int nt = wc * 2 + nn;
#pragma unroll
        for (int ks = 0; ks < 4; ks++) {
            uint32_t bf[2];
            ldmx2(bf, &wWls[(nt * 8 + (lane & 7)) * APAD + ks * 16 + ((lane >> 3) & 1) * 8]);
            mma16816(C[nn], af[ks], bf);
        }
    }

    // stage A epilogue -> ycs (bf16)
#pragma unroll
    for (int nn = 0; nn < 2; nn++) {
        int i2 = (wc * 2 + nn) * 8 + tig * 2;
        float sc0 = gWl[i2] * rs, sc1 = gWl[i2 + 1] * rs;
        float bb0 = betaWl[i2], bb1 = betaWl[i2 + 1];
        float2 yn0 = unpackbf(*(uint32_t*)&ynlS[px0 * APAD + i2]);
        float2 yn1 = unpackbf(*(uint32_t*)&ynlS[(px0 + 8) * APAD + i2]);
        *(uint32_t*)&ycs[px0 * APAD + i2] =
            packbf(yn0.x + fmaxf(C[nn][0], 0.f) * sc0 + bb0,
                   yn0.y + fmaxf(C[nn][1], 0.f) * sc1 + bb1);
        *(uint32_t*)&ycs[(px0 + 8) * APAD + i2] =
            packbf(yn1.x + fmaxf(C[nn][2], 0.f) * sc0 + bb0,
                   yn1.y + fmaxf(C[nn][3], 0.f) * sc1 + bb1);
    }
    __syncthreads();

    // stage B GEMM: C2[px][o] = yc @ wW^T — each warp: 4 of 16 nt
    uint32_t af2[4][4];
    {
        const __nv_bfloat16* ab = &ycs[(wr * 16 + (lane & 15)) * APAD + (lane >> 4) * 8];
#pragma unroll
        for (int ks = 0; ks < 4; ks++) ldmx4(af2[ks], ab + ks * 16);
    }
    __syncthreads();   // ycs consumed -> outS may alias

    float C2[4][4];
#pragma unroll
    for (int nn = 0; nn < 4; nn++) C2[nn][0] = C2[nn][1] = C2[nn][2] = C2[nn][3] = 0.f;
#pragma unroll
    for (int nn = 0; nn < 4; nn++) {
        int nt = wc * 4 + nn;
#pragma unroll
        for (int ks = 0; ks < 4; ks++) {
            uint32_t bf[2];
            ldmx2(bf, &wWs[(nt * 8 + (lane & 7)) * APAD + ks * 16 + ((lane >> 3) & 1) * 8]);
            mma16816(C2[nn], af2[ks], bf);
        }
    }

    // stage B epilogue -> outS (fp32, [o][px] stride 36)
#pragma unroll
    for (int nn = 0; nn < 4; nn++) {
        int o2 = (wc * 4 + nn) * 8 + tig * 2;
        float bw0 = bW[o2], bw1 = bW[o2 + 1];
        float sc0 = gW[o2] * rs, sc1 = gW[o2 + 1] * rs;
        float bt0 = betaW[o2], bt1 = betaW[o2 + 1];
        outS[o2 * 36 + px0]           = fmaxf(C2[nn][0] + bw0, 0.f) * sc0 + bt0;
        outS[(o2 + 1) * 36 + px0]     = fmaxf(C2[nn][1] + bw1, 0.f) * sc1 + bt1;
        outS[o2 * 36 + px0 + 8]       = fmaxf(C2[nn][2] + bw0, 0.f) * sc0 + bt0;
        outS[(o2 + 1) * 36 + px0 + 8] = fmaxf(C2[nn][3] + bw1, 0.f) * sc1 + bt1;
    }
    __syncthreads();

    // coalesced residual add + store (128 o x 32 px)
    for (int idx = t; idx < 1024; idx += 256) {
        int o = idx >> 3, p4 = (idx & 7) * 4;
        size_t base = ((size_t)b * CDIM + o) * NPIX + n0 + p4;
        float4 s = *(float4*)&outS[o * 36 + p4];
        float4 xv = *(const float4*)&x[base];
        float4 z = make_float4(s.x + xv.x, s.y + xv.y, s.z + xv.z, s.w + xv.w);
        *(float4*)&out[base] = z;
    }
}

// ---------------- launch ----------------
extern "C" void kernel_launch(void* const* d_in, const int* in_sizes, int n_in,
                              void* d_out, int out_size) {
    const float* x      = (const float*)d_in[0];
    const float* mask   = (const float*)d_in[1];
    const float* wt_nl  = (const float*)d_in[2];
    const float* bt_nl  = (const float*)d_in[3];
    const float* wp_nl  = (const float*)d_in[4];
    const float* bp_nl  = (const float*)d_in[5];
    const float* wt_l   = (const float*)d_in[6];
    const float* bt_l   = (const float*)d_in[7];
    const float* wp_l   = (const float*)d_in[8];
    const float* bp_l   = (const float*)d_in[9];
    const float* wg_nl  = (const float*)d_in[10];
    const float* bg_nl  = (const float*)d_in[11];
    const float* wg_l   = (const float*)d_in[12];
    const float* bg_l   = (const float*)d_in[13];
    const float* wW     = (const float*)d_in[14];
    const float* bW     = (const float*)d_in[15];
    const float* gW     = (const float*)d_in[16];
    const float* betaW  = (const float*)d_in[17];
    const float* wWl    = (const float*)d_in[18];
    const float* gWl    = (const float*)d_in[19];
    const float* betaWl = (const float*)d_in[20];
    float* out = (float*)d_out;

    cudaFuncSetAttribute(attn_kernel, cudaFuncAttributeMaxDynamicSharedMemorySize,
                         ATTN_DSMEM);
    cudaFuncSetAttribute(epi_kernel, cudaFuncAttributeMaxDynamicSharedMemorySize,
                         EPI_DSMEM);

    prep_wt_kernel<<<60, 1024>>>(wt_nl, wp_nl, wt_l, wp_l, wg_nl, wg_l, wWl, wW);
    proj_kernel<<<dim3(64, 4), 128>>>(x, mask, bt_nl, bp_nl, bt_l, bp_l, bg_nl, bg_l);
    attn_kernel<<<dim3(32, 4, 2), 256, ATTN_DSMEM>>>();
    epi_kernel<<<dim3(128, 4), 256, EPI_DSMEM>>>(x, gWl, betaWl, bW, gW, betaW, out);
}

// round 16
// speedup vs baseline: 1.0291x; 1.0291x over previous
#include <cuda_runtime.h>
#include <cuda_bf16.h>
#include <cstdint>

#define BATCH 4
#define CDIM 128
#define IDIM 64
#define NPIX 4096
#define LOG2E 1.4426950408889634f
#define SKV 72

// ---------------- device scratch ----------------
__device__ __align__(128) __nv_bfloat16 g_Wb[6 * CDIM * IDIM];                   // [p][c][i] bf16
__device__ __align__(128) __nv_bfloat16 g_WlB[IDIM * IDIM];                      // wWl bf16
__device__ __align__(128) __nv_bfloat16 g_WB[CDIM * IDIM];                       // wW  bf16
__device__ __align__(128) __nv_bfloat16 g_proj[(size_t)6 * BATCH * NPIX * IDIM]; // [p][b][n][i]
__device__ __align__(128) __nv_bfloat16 g_yb[(size_t)2 * BATCH * NPIX * IDIM];   // [br][b][n][i] bf16

// ---------------- generic helpers ----------------
__device__ __forceinline__ uint32_t smaddr(const void* p) {
    return (uint32_t)__cvta_generic_to_shared(p);
}
__device__ __forceinline__ uint32_t packbf(float lo, float hi) {
    uint32_t r;
    asm("cvt.rn.bf16x2.f32 %0, %1, %2;" : "=r"(r) : "f"(hi), "f"(lo));
    return r;
}
__device__ __forceinline__ float2 unpackbf(uint32_t u) {
    __nv_bfloat162 h = *(__nv_bfloat162*)&u;
    return make_float2(__bfloat162float(h.x), __bfloat162float(h.y));
}
__device__ __forceinline__ uint32_t ex2b(uint32_t x) {   // 2^x on packed bf16x2
    uint32_t y;
    asm("ex2.approx.ftz.bf16x2 %0, %1;" : "=r"(y) : "r"(x));
    return y;
}
__device__ __forceinline__ void cpa16(uint32_t dst, const void* src) {
    asm volatile("cp.async.cg.shared.global [%0], [%1], 16;" :: "r"(dst), "l"(src));
}
#define CP_COMMIT asm volatile("cp.async.commit_group;")
#define CP_WAIT(n) asm volatile("cp.async.wait_group %0;" :: "n"(n))

// ---------------- mma helpers ----------------
__device__ __forceinline__ void ldmx4(uint32_t r[4], const void* p) {
    asm volatile("ldmatrix.sync.aligned.m8n8.x4.shared.b16 {%0,%1,%2,%3}, [%4];"
                 : "=r"(r[0]), "=r"(r[1]), "=r"(r[2]), "=r"(r[3]) : "r"(smaddr(p)));
}
__device__ __forceinline__ void ldmx4t(uint32_t r[4], const void* p) {
    asm volatile("ldmatrix.sync.aligned.m8n8.x4.trans.shared.b16 {%0,%1,%2,%3}, [%4];"
                 : "=r"(r[0]), "=r"(r[1]), "=r"(r[2]), "=r"(r[3]) : "r"(smaddr(p)));
}
__device__ __forceinline__ void ldmx2(uint32_t r[2], const void* p) {
    asm volatile("ldmatrix.sync.aligned.m8n8.x2.shared.b16 {%0,%1}, [%2];"
                 : "=r"(r[0]), "=r"(r[1]) : "r"(smaddr(p)));
}
__device__ __forceinline__ void ldmx2t(uint32_t r[2], const void* p) {
    asm volatile("ldmatrix.sync.aligned.m8n8.x2.trans.shared.b16 {%0,%1}, [%2];"
                 : "=r"(r[0]), "=r"(r[1]) : "r"(smaddr(p)));
}
__device__ __forceinline__ void mma16816(float d[4], const uint32_t a[4], const uint32_t b[2]) {
    asm volatile("mma.sync.aligned.m16n8k16.row.col.f32.bf16.bf16.f32 "
                 "{%0,%1,%2,%3}, {%4,%5,%6,%7}, {%8,%9}, {%0,%1,%2,%3};"
                 : "+f"(d[0]), "+f"(d[1]), "+f"(d[2]), "+f"(d[3])
                 : "r"(a[0]), "r"(a[1]), "r"(a[2]), "r"(a[3]), "r"(b[0]), "r"(b[1]));
}

// ---------------- kernel 0: weight prep ----------------
__global__ void prep_wt_kernel(const float* __restrict__ w0, const float* __restrict__ w1,
                               const float* __restrict__ w2, const float* __restrict__ w3,
                               const float* __restrict__ w4, const float* __restrict__ w5,
                               const float* __restrict__ wWl, const float* __restrict__ wW) {
    int idx = blockIdx.x * blockDim.x + threadIdx.x;
    if (idx < 6 * CDIM * IDIM) {
        int p = idx / (CDIM * IDIM);
        int r = idx % (CDIM * IDIM);
        int c = r / IDIM, i = r % IDIM;
        const float* w = (p == 0) ? w0 : (p == 1) ? w1 : (p == 2) ? w2 : (p == 3) ? w3 : (p == 4) ? w4 : w5;
        float s = (p == 0 || p == 2) ? LOG2E : 1.0f;
        g_Wb[idx] = __float2bfloat16(w[i * CDIM + c] * s);
    } else if (idx < 6 * CDIM * IDIM + IDIM * IDIM) {
        int k = idx - 6 * CDIM * IDIM;
        g_WlB[k] = __float2bfloat16(wWl[k]);
    } else if (idx < 6 * CDIM * IDIM + IDIM * IDIM + CDIM * IDIM) {
        int k = idx - 6 * CDIM * IDIM - IDIM * IDIM;
        g_WB[k] = __float2bfloat16(wW[k]);
    }
}

// ---------------- kernel 1: fused projections (p-split: 3 projections per block) ----------------
#define APAD 72
__global__ __launch_bounds__(128) void proj_kernel(
    const float* __restrict__ x, const float* __restrict__ mask,
    const float* __restrict__ b0, const float* __restrict__ b1,
    const float* __restrict__ b2, const float* __restrict__ b3,
    const float* __restrict__ b4, const float* __restrict__ b5)
{
    __shared__ __align__(16) __nv_bfloat16 As[CDIM * APAD];   // [c][px]
    __shared__ __align__(16) __nv_bfloat16 Bs[CDIM * APAD];   // [c][i]
    __shared__ float maskS[64];

    int n0 = blockIdx.x * 64;
    int b  = blockIdx.y;
    int ph = blockIdx.z;           // 0 -> p 0..2, 1 -> p 3..5
    int t  = threadIdx.x;
    int lane = t & 31, w = t >> 5;
    int gID = lane >> 2, tig = lane & 3;

    for (int idx = t; idx < 1024; idx += 128) {
        int c = idx >> 3, px0 = (idx & 7) * 8;
        const float* xr = x + ((size_t)b * CDIM + c) * NPIX + n0 + px0;
        float4 v0 = *(const float4*)xr;
        float4 v1 = *(const float4*)(xr + 4);
        uint4 pk;
        pk.x = packbf(v0.x, v0.y); pk.y = packbf(v0.z, v0.w);
        pk.z = packbf(v1.x, v1.y); pk.w = packbf(v1.z, v1.w);
        *(uint4*)&As[c * APAD + px0] = pk;
    }
    if (t < 64) maskS[t] = mask[(size_t)b * NPIX + n0 + t];
    __syncthreads();

    uint32_t af[8][4];
#pragma unroll
    for (int kt = 0; kt < 8; kt++) {
        const __nv_bfloat16* ap =
            &As[(kt * 16 + (lane & 7) + ((lane >> 4) << 3)) * APAD + w * 16 + (((lane >> 3) & 1) << 3)];
        ldmx4t(af[kt], ap);
    }

    const float* biases[6] = {b0, b1, b2, b3, b4, b5};
    int px0 = w * 16 + gID;

#pragma unroll
    for (int pp = 0; pp < 3; pp++) {
        int p = ph * 3 + pp;
        __syncthreads();
        const __nv_bfloat16* wsrc = g_Wb + p * (CDIM * IDIM);
        for (int idx = t; idx < 512; idx += 128) {
            int c = idx >> 2, c8 = (idx & 3) * 16;
            *(uint4*)&Bs[c * APAD + c8]     = *(const uint4*)&wsrc[c * IDIM + c8];
            *(uint4*)&Bs[c * APAD + c8 + 8] = *(const uint4*)&wsrc[c * IDIM + c8 + 8];
        }
        __syncthreads();

        float C[8][4];
#pragma unroll
        for (int nt = 0; nt < 8; nt++) C[nt][0] = C[nt][1] = C[nt][2] = C[nt][3] = 0.f;
#pragma unroll
        for (int kt = 0; kt < 8; kt++) {
#pragma unroll
            for (int nt = 0; nt < 8; nt++) {
                uint32_t bf[2];
                ldmx2t(bf, &Bs[(kt * 16 + (lane & 15)) * APAD + nt * 8]);
                mma16816(C[nt], af[kt], bf);
            }
        }

        bool um = (p == 2 || p == 3);
        float bscale = (p == 0 || p == 2) ? LOG2E : 1.0f;
        float mv0 = um ? maskS[px0] : 1.f;
        float mv1 = um ? maskS[px0 + 8] : 1.f;
        const float* biasp = biases[p];

        __nv_bfloat16* outp = g_proj + ((size_t)(p * BATCH + b) * NPIX + n0) * IDIM;
#pragma unroll
        for (int nt = 0; nt < 8; nt++) {
            int i2 = nt * 8 + tig * 2;
            float bb0 = biasp[i2] * bscale, bb1 = biasp[i2 + 1] * bscale;
            *(uint32_t*)&outp[(size_t)px0 * IDIM + i2] =
                packbf((C[nt][0] + bb0) * mv0, (C[nt][1] + bb1) * mv0);
            *(uint32_t*)&outp[(size_t)(px0 + 8) * IDIM + i2] =
                packbf((C[nt][2] + bb0) * mv1, (C[nt][3] + bb1) * mv1);
        }
    }
}

// ---------------- kernel 2: flash attention (exact R11/R14 measured body) ----------------
#define ATTN_DSMEM (2 * 128 * SKV * 2)

__global__ __launch_bounds__(256, 2) void attn_kernel() {
    extern __shared__ __align__(16) uint8_t dynsm[];
    int qt = blockIdx.x, b = blockIdx.y, br = blockIdx.z;
    int t = threadIdx.x, lane = t & 31, w = t >> 5;
    int gID = lane >> 2, tig = lane & 3;

    __nv_bfloat16* stage0 = (__nv_bfloat16*)dynsm;
    __nv_bfloat16* stage1 = (__nv_bfloat16*)(dynsm + 128 * SKV * 2);

    const __nv_bfloat16* Qg = g_proj + ((size_t)(br * 2 + 0) * BATCH + b) * NPIX * IDIM
                                     + (size_t)qt * 128 * IDIM;
    const __nv_bfloat16* Kg = g_proj + ((size_t)(br * 2 + 1) * BATCH + b) * NPIX * IDIM;
    const __nv_bfloat16* Vg = g_proj + ((size_t)(4 + br) * BATCH + b) * NPIX * IDIM;

    for (int idx = t; idx < 1024; idx += 256) {
        int r = idx >> 3, c8 = (idx & 7) * 8;
        *(uint4*)&stage0[r * SKV + c8] = *(const uint4*)&Qg[(size_t)r * IDIM + c8];
    }
    __syncthreads();
    uint32_t qa[4][4];
    {
        const __nv_bfloat16* qbase = &stage0[(w * 16 + (lane & 15)) * SKV + (lane >> 4) * 8];
#pragma unroll
        for (int kk = 0; kk < 4; kk++) ldmx4(qa[kk], qbase + kk * 16);
    }
    __syncthreads();

    __nv_bfloat16* stg[2] = {stage0, stage1};
#pragma unroll
    for (int s = 0; s < 2; s++) {
        const __nv_bfloat16* Kt = Kg + (size_t)s * 64 * IDIM;
        const __nv_bfloat16* Vt = Vg + (size_t)s * 64 * IDIM;
        for (int idx = t; idx < 512; idx += 256) {
            int r = idx >> 3, c8 = (idx & 7) * 8;
            cpa16(smaddr(&stg[s][r * SKV + c8]), &Kt[(size_t)r * IDIM + c8]);
            cpa16(smaddr(&stg[s][64 * SKV + r * SKV + c8]), &Vt[(size_t)r * IDIM + c8]);
        }
        CP_COMMIT;
    }

    const uint32_t ones2[2] = {0x3F803F80u, 0x3F803F80u};
    float Lacc[4] = {0.f, 0.f, 0.f, 0.f};
    float O[8][4];
#pragma unroll
    for (int d = 0; d < 8; d++) O[d][0] = O[d][1] = O[d][2] = O[d][3] = 0.f;

    for (int kt = 0; kt < 64; kt++) {
        CP_WAIT(1);
        __syncthreads();
        const __nv_bfloat16* Ks = stg[kt & 1];
        const __nv_bfloat16* Vs = Ks + 64 * SKV;

        float S[8][4];
#pragma unroll
        for (int nt = 0; nt < 8; nt++) {
            S[nt][0] = S[nt][1] = S[nt][2] = S[nt][3] = 0.f;
#pragma unroll
            for (int ks = 0; ks < 4; ks++) {
                uint32_t kb[2];
                ldmx2(kb, &Ks[(nt * 8 + (lane & 7)) * SKV + ks * 16 + ((lane >> 3) & 1) * 8]);
                mma16816(S[nt], qa[ks], kb);
            }
        }

        uint32_t pa[4][4];
#pragma unroll
        for (int nt = 0; nt < 8; nt++) {
            pa[nt >> 1][(nt & 1) * 2 + 0] = ex2b(packbf(S[nt][0], S[nt][1]));
            pa[nt >> 1][(nt & 1) * 2 + 1] = ex2b(packbf(S[nt][2], S[nt][3]));
        }

#pragma unroll
        for (int ks = 0; ks < 4; ks++) mma16816(Lacc, pa[ks], ones2);

#pragma unroll
        for (int d = 0; d < 8; d++) {
#pragma unroll
            for (int ks = 0; ks < 4; ks++) {
                uint32_t vb[2];
                ldmx2t(vb, &Vs[(ks * 16 + (lane & 15)) * SKV + d * 8]);
                mma16816(O[d], pa[ks], vb);
            }
        }
        __syncthreads();
        if (kt + 2 < 64) {
            const __nv_bfloat16* Kt = Kg + (size_t)(kt + 2) * 64 * IDIM;
            const __nv_bfloat16* Vt = Vg + (size_t)(kt + 2) * 64 * IDIM;
            __nv_bfloat16* dst = stg[kt & 1];
            for (int idx = t; idx < 512; idx += 256) {
                int r = idx >> 3, c8 = (idx & 7) * 8;
                cpa16(smaddr(&dst[r * SKV + c8]), &Kt[(size_t)r * IDIM + c8]);
                cpa16(smaddr(&dst[64 * SKV + r * SKV + c8]), &Vt[(size_t)r * IDIM + c8]);
            }
        }
        CP_COMMIT;
    }

    float inv0 = 1.f / Lacc[0], inv1 = 1.f / Lacc[2];

    int r0 = qt * 128 + w * 16 + gID;
    __nv_bfloat16* yb = g_yb + ((size_t)br * BATCH + b) * NPIX * IDIM;
#pragma unroll
    for (int d = 0; d < 8; d++) {
        int col = d * 8 + tig * 2;
        *(uint32_t*)&yb[(size_t)r0 * IDIM + col] =
            packbf(O[d][0] * inv0, O[d][1] * inv0);
        *(uint32_t*)&yb[(size_t)(r0 + 8) * IDIM + col] =
            packbf(O[d][2] * inv1, O[d][3] * inv1);
    }
}

// ---------------- kernel 3: tensor-core fused epilogue, 32-px tiles (R15 measured) ----------------
#define EPI_DSMEM 41472
__global__ __launch_bounds__(256) void epi_kernel(
    const float* __restrict__ x,
    const float* __restrict__ gWl, const float* __restrict__ betaWl,
    const float* __restrict__ bW,  const float* __restrict__ gW,
    const float* __restrict__ betaW,
    float* __restrict__ out)
{
    extern __shared__ __align__(16) uint8_t esm[];
    __nv_bfloat16* yls  = (__nv_bfloat16*)(esm);
    __nv_bfloat16* ynlS = (__nv_bfloat16*)(esm + 4608);
    __nv_bfloat16* ycs  = (__nv_bfloat16*)(esm + 9216);
    __nv_bfloat16* wWls = (__nv_bfloat16*)(esm + 13824);
    __nv_bfloat16* wWs  = (__nv_bfloat16*)(esm + 23040);
    float*         outS = (float*)(esm);          // aliases yls/ynlS/ycs/part of wWls

    int b = blockIdx.y, n0 = blockIdx.x * 32;
    int t = threadIdx.x, lane = t & 31, w = t >> 5;
    int gID = lane >> 2, tig = lane & 3;
    int wr = w & 1;          // row group (16 px)
    int wc = w >> 1;         // column quarter (0..3)

    const __nv_bfloat16* ylg  = g_yb + ((size_t)(BATCH + b) * NPIX + n0) * IDIM;
    const __nv_bfloat16* ynlg = g_yb + ((size_t)b * NPIX + n0) * IDIM;

    {
        int r = t >> 3, c8 = (t & 7) * 8;
        *(uint4*)&yls[r * APAD + c8]  = *(const uint4*)&ylg[(size_t)r * IDIM + c8];
        *(uint4*)&ynlS[r * APAD + c8] = *(const uint4*)&ynlg[(size_t)r * IDIM + c8];
    }
    for (int idx = t; idx < 512; idx += 256) {
        int r = idx >> 3, c8 = (idx & 7) * 8;
        *(uint4*)&wWls[r * APAD + c8] = *(const uint4*)&g_WlB[r * IDIM + c8];
    }
    for (int idx = t; idx < 1024; idx += 256) {
        int r = idx >> 3, c8 = (idx & 7) * 8;
        *(uint4*)&wWs[r * APAD + c8] = *(const uint4*)&g_WB[r * IDIM + c8];
    }
    __syncthreads();

    float rs = rsqrtf(1.0f + 1e-5f);
    int px0 = wr * 16 + gID;

    uint32_t af[4][4];
    {
        const __nv_bfloat16* ab = &yls[(wr * 16 + (lane & 15)) * APAD + (lane >> 4) * 8];
#pragma unroll
        for (int ks = 0; ks < 4; ks++) ldmx4(af[ks], ab + ks * 16);
    }
    float C[2][4];
#pragma unroll
    for (int nn = 0; nn < 2; nn++) C[nn][0] = C[nn][1] = C[nn][2] = C[nn][3] = 0.f;
#pragma unroll
    for (int nn = 0; nn < 2; nn++) {
        int nt = wc * 2 + nn;
#pragma unroll
        for (int ks = 0; ks < 4; ks++) {
            uint32_t bf[2];
            ldmx2(bf, &wWls[(nt * 8 + (lane & 7)) * APAD + ks * 16 + ((lane >> 3) & 1) * 8]);
            mma16816(C[nn], af[ks], bf);
        }
    }

#pragma unroll
    for (int nn = 0; nn < 2; nn++) {
        int i2 = (wc * 2 + nn) * 8 + tig * 2;
        float sc0 = gWl[i2] * rs, sc1 = gWl[i2 + 1] * rs;
        float bb0 = betaWl[i2], bb1 = betaWl[i2 + 1];
        float2 yn0 = unpackbf(*(uint32_t*)&ynlS[px0 * APAD + i2]);
        float2 yn1 = unpackbf(*(uint32_t*)&ynlS[(px0 + 8) * APAD + i2]);
        *(uint32_t*)&ycs[px0 * APAD + i2] =
            packbf(yn0.x + fmaxf(C[nn][0], 0.f) * sc0 + bb0,
                   yn0.y + fmaxf(C[nn][1], 0.f) * sc1 + bb1);
        *(uint32_t*)&ycs[(px0 + 8) * APAD + i2] =
            packbf(yn1.x + fmaxf(C[nn][2], 0.f) * sc0 + bb0,
                   yn1.y + fmaxf(C[nn][3], 0.f) * sc1 + bb1);
    }
    __syncthreads();

    uint32_t af2[4][4];
    {
        const __nv_bfloat16* ab = &ycs[(wr * 16 + (lane & 15)) * APAD + (lane >> 4) * 8];
#pragma unroll
        for (int ks = 0; ks < 4; ks++) ldmx4(af2[ks], ab + ks * 16);
    }
    __syncthreads();   // ycs consumed -> outS may alias

    float C2[4][4];
#pragma unroll
    for (int nn = 0; nn < 4; nn++) C2[nn][0] = C2[nn][1] = C2[nn][2] = C2[nn][3] = 0.f;
#pragma unroll
    for (int nn = 0; nn < 4; nn++) {
        int nt = wc * 4 + nn;
#pragma unroll
        for (int ks = 0; ks < 4; ks++) {
            uint32_t bf[2];
            ldmx2(bf, &wWs[(nt * 8 + (lane & 7)) * APAD + ks * 16 + ((lane >> 3) & 1) * 8]);
            mma16816(C2[nn], af2[ks], bf);
        }
    }

#pragma unroll
    for (int nn = 0; nn < 4; nn++) {
        int o2 = (wc * 4 + nn) * 8 + tig * 2;
        float bw0 = bW[o2], bw1 = bW[o2 + 1];
        float sc0 = gW[o2] * rs, sc1 = gW[o2 + 1] * rs;
        float bt0 = betaW[o2], bt1 = betaW[o2 + 1];
        outS[o2 * 36 + px0]           = fmaxf(C2[nn][0] + bw0, 0.f) * sc0 + bt0;
        outS[(o2 + 1) * 36 + px0]     = fmaxf(C2[nn][1] + bw1, 0.f) * sc1 + bt1;
        outS[o2 * 36 + px0 + 8]       = fmaxf(C2[nn][2] + bw0, 0.f) * sc0 + bt0;
        outS[(o2 + 1) * 36 + px0 + 8] = fmaxf(C2[nn][3] + bw1, 0.f) * sc1 + bt1;
    }
    __syncthreads();

    for (int idx = t; idx < 1024; idx += 256) {
        int o = idx >> 3, p4 = (idx & 7) * 4;
        size_t base = ((size_t)b * CDIM + o) * NPIX + n0 + p4;
        float4 s = *(float4*)&outS[o * 36 + p4];
        float4 xv = *(const float4*)&x[base];
        float4 z = make_float4(s.x + xv.x, s.y + xv.y, s.z + xv.z, s.w + xv.w);
        *(float4*)&out[base] = z;
    }
}

// ---------------- launch ----------------
extern "C" void kernel_launch(void* const* d_in, const int* in_sizes, int n_in,
                              void* d_out, int out_size) {
    const float* x      = (const float*)d_in[0];
    const float* mask   = (const float*)d_in[1];
    const float* wt_nl  = (const float*)d_in[2];
    const float* bt_nl  = (const float*)d_in[3];
    const float* wp_nl  = (const float*)d_in[4];
    const float* bp_nl  = (const float*)d_in[5];
    const float* wt_l   = (const float*)d_in[6];
    const float* bt_l   = (const float*)d_in[7];
    const float* wp_l   = (const float*)d_in[8];
    const float* bp_l   = (const float*)d_in[9];
    const float* wg_nl  = (const float*)d_in[10];
    const float* bg_nl  = (const float*)d_in[11];
    const float* wg_l   = (const float*)d_in[12];
    const float* bg_l   = (const float*)d_in[13];
    const float* wW     = (const float*)d_in[14];
    const float* bW     = (const float*)d_in[15];
    const float* gW     = (const float*)d_in[16];
    const float* betaW  = (const float*)d_in[17];
    const float* wWl    = (const float*)d_in[18];
    const float* gWl    = (const float*)d_in[19];
    const float* betaWl = (const float*)d_in[20];
    float* out = (float*)d_out;

    cudaFuncSetAttribute(attn_kernel, cudaFuncAttributeMaxDynamicSharedMemorySize,
                         ATTN_DSMEM);
    cudaFuncSetAttribute(epi_kernel, cudaFuncAttributeMaxDynamicSharedMemorySize,
                         EPI_DSMEM);

    prep_wt_kernel<<<60, 1024>>>(wt_nl, wp_nl, wt_l, wp_l, wg_nl, wg_l, wWl, wW);
    proj_kernel<<<dim3(64, 4, 2), 128>>>(x, mask, bt_nl, bp_nl, bt_l, bp_l, bg_nl, bg_l);
    attn_kernel<<<dim3(32, 4, 2), 256, ATTN_DSMEM>>>();
    epi_kernel<<<dim3(128, 4), 256, EPI_DSMEM>>>(x, gWl, betaWl, bW, gW, betaW, out);
}